// round 8
// baseline (speedup 1.0000x reference)
#include <cuda_runtime.h>
#include <cuda.h>
#include <cuda_fp16.h>
#include <cstdint>
#include <cstddef>
#include <cstring>

// ---------------------------------------------------------------------------
// Problem constants
// ---------------------------------------------------------------------------
#define M_TOT 8192        // B*S
#define N_TOT 4096        // D_OUT
#define K_TOT 4096        // D_IN
#define RANK  16
#define K2    4160        // K + 64 (lora tail chunk, padded)
#define NCHUNK 65         // K2 / 64
#define STAGES 3
#define GEMM_THREADS 256

// smem layout (bytes, relative to dynamic smem base; base is 1024-aligned)
#define OFF_FULL   0      // 3 x 8B
#define OFF_EMPTY  32     // 3 x 8B
#define OFF_BIAS   64     // 128 floats
#define OFF_TILES  1024
#define TILE_BYTES 16384  // 128 rows x 128B (64 fp16)
#define SMEM_TOTAL (OFF_TILES + 2 * STAGES * TILE_BYTES)   // 99328

// ---------------------------------------------------------------------------
// Device scratch (allocation-free rule: __device__ globals)
// ---------------------------------------------------------------------------
__device__ __half g_xh[(size_t)M_TOT * K2];   // [8192, 4160] fp16  ~68 MB
__device__ __half g_wb[(size_t)N_TOT * K2];   // [4096, 4160] fp16  ~34 MB

// ---------------------------------------------------------------------------
// PTX helpers (family-portable: TMA + mbarrier + ldmatrix + mma.sync only)
// ---------------------------------------------------------------------------
__device__ __forceinline__ uint32_t smem_u32(const void* p) {
    uint32_t a;
    asm("{ .reg .u64 t; cvta.to.shared.u64 t, %1; cvt.u32.u64 %0, t; }"
        : "=r"(a) : "l"(p));
    return a;
}
__device__ __forceinline__ void mbar_init(uint32_t a, uint32_t n) {
    asm volatile("mbarrier.init.shared.b64 [%0], %1;" :: "r"(a), "r"(n) : "memory");
}
__device__ __forceinline__ void mbar_expect_tx(uint32_t a, uint32_t bytes) {
    asm volatile("mbarrier.arrive.expect_tx.shared.b64 _, [%0], %1;"
                 :: "r"(a), "r"(bytes) : "memory");
}
__device__ __forceinline__ void mbar_arrive(uint32_t a) {
    asm volatile("mbarrier.arrive.shared.b64 _, [%0];" :: "r"(a) : "memory");
}
__device__ __forceinline__ void mbar_wait(uint32_t a, uint32_t parity) {
    asm volatile(
        "{\n\t.reg .pred P;\n"
        "W_%=:\n\t"
        "mbarrier.try_wait.parity.acquire.cta.shared::cta.b64 P, [%0], %1, 0x989680;\n\t"
        "@P bra D_%=;\n\t"
        "bra W_%=;\n"
        "D_%=:\n\t}"
        :: "r"(a), "r"(parity) : "memory");
}
__device__ __forceinline__ void tma_2d(uint32_t dst, const CUtensorMap* tm,
                                       int cx, int cy, uint32_t mbar) {
    asm volatile(
        "cp.async.bulk.tensor.2d.shared::cta.global.tile.mbarrier::complete_tx::bytes "
        "[%0], [%1, {%2, %3}], [%4];"
        :: "r"(dst), "l"(tm), "r"(cx), "r"(cy), "r"(mbar) : "memory");
}
__device__ __forceinline__ void ldsm4(uint32_t& r0, uint32_t& r1, uint32_t& r2,
                                      uint32_t& r3, uint32_t addr) {
    asm volatile("ldmatrix.sync.aligned.m8n8.x4.shared.b16 {%0,%1,%2,%3}, [%4];"
                 : "=r"(r0), "=r"(r1), "=r"(r2), "=r"(r3) : "r"(addr));
}
__device__ __forceinline__ void mma16816(float& d0, float& d1, float& d2, float& d3,
                                         uint32_t a0, uint32_t a1, uint32_t a2, uint32_t a3,
                                         uint32_t b0, uint32_t b1) {
    asm volatile(
        "mma.sync.aligned.m16n8k16.row.col.f32.f16.f16.f32 "
        "{%0,%1,%2,%3}, {%4,%5,%6,%7}, {%8,%9}, {%0,%1,%2,%3};"
        : "+f"(d0), "+f"(d1), "+f"(d2), "+f"(d3)
        : "r"(a0), "r"(a1), "r"(a2), "r"(a3), "r"(b0), "r"(b1));
}

// ---------------------------------------------------------------------------
// Kernel 1 (FUSED): t = x @ lora_A  AND  g_xh = fp16(x) | fp16(t) | 0
// Streams x exactly once. 16 m-rows per block, 256 threads.
// ---------------------------------------------------------------------------
__global__ void __launch_bounds__(256) lora_prep_x_kernel(const float* __restrict__ x,
                                                          const float* __restrict__ A) {
    __shared__ float sX[16][132];
    __shared__ float sAT[RANK][132];
    int tid = threadIdx.x;
    int m0 = blockIdx.x * 16;
    int ml = tid >> 4, r = tid & 15;
    float acc = 0.f;

    for (int k0 = 0; k0 < K_TOT; k0 += 128) {
        __syncthreads();
        // load x tile [16][128] as float4; also emit fp16 to g_xh from registers
        #pragma unroll
        for (int it = 0; it < 2; it++) {
            int idx = tid + it * 256;
            int row = idx >> 5, col = idx & 31;
            float4 v = ((const float4*)(x + (size_t)(m0 + row) * K_TOT + k0))[col];
            ((float4*)&sX[row][0])[col] = v;
            __half2 h01 = __floats2half2_rn(v.x, v.y);
            __half2 h23 = __floats2half2_rn(v.z, v.w);
            __half2 hp[2] = {h01, h23};
            uint2 u;
            memcpy(&u, hp, 8);
            *(uint2*)(g_xh + (size_t)(m0 + row) * K2 + k0 + col * 4) = u;
        }
        // load A chunk transposed
        #pragma unroll
        for (int it = 0; it < 2; it++) {
            int idx = tid + it * 256;
            int k = idx >> 2, q = idx & 3;
            float4 a = ((const float4*)(A + (size_t)(k0 + k) * RANK))[q];
            sAT[q * 4 + 0][k] = a.x;
            sAT[q * 4 + 1][k] = a.y;
            sAT[q * 4 + 2][k] = a.z;
            sAT[q * 4 + 3][k] = a.w;
        }
        __syncthreads();
        const float4* xr = (const float4*)&sX[ml][0];
        const float4* ar = (const float4*)&sAT[r][0];
        #pragma unroll 8
        for (int kk = 0; kk < 32; kk++) {
            float4 xv = xr[kk];
            float4 av = ar[kk];
            acc += xv.x * av.x + xv.y * av.y + xv.z * av.z + xv.w * av.w;
        }
    }
    // tail: cols [4096,4112) = fp16(t); cols [4112,4160) = 0
    g_xh[(size_t)(m0 + ml) * K2 + K_TOT + r] = __float2half_rn(acc);
    for (int j = tid; j < 16 * 48; j += 256) {
        int row = j / 48, col = j - row * 48;
        g_xh[(size_t)(m0 + row) * K2 + 4112 + col] = __ushort_as_half((unsigned short)0);
    }
}

// ---------------------------------------------------------------------------
// Kernel 2: B-side main region, vectorized: 8 int32 -> 8 fp16 per thread
//   grid = (2, 4096); no integer division anywhere
// ---------------------------------------------------------------------------
__global__ void __launch_bounds__(256) prep_w_main_kernel(const int* __restrict__ q) {
    int n = blockIdx.y;
    int c0 = (blockIdx.x * 256 + threadIdx.x) * 8;
    const int4* qp = (const int4*)(q + (size_t)n * K_TOT + c0);
    int4 q0 = qp[0], q1 = qp[1];
    __half2 h[4];
    h[0] = __floats2half2_rn((float)q0.x, (float)q0.y);
    h[1] = __floats2half2_rn((float)q0.z, (float)q0.w);
    h[2] = __floats2half2_rn((float)q1.x, (float)q1.y);
    h[3] = __floats2half2_rn((float)q1.z, (float)q1.w);
    uint4 u;
    memcpy(&u, h, 16);
    *(uint4*)(g_wb + (size_t)n * K2 + c0) = u;
}

// ---------------------------------------------------------------------------
// Kernel 3: B-side tail: cols [4096,4112) = fp16(lora_B[r][n]/scale); rest 0
//   grid = 4096 blocks x 64 threads
// ---------------------------------------------------------------------------
__global__ void __launch_bounds__(64) prep_w_tail_kernel(const float* __restrict__ lB,
                                                         const float* __restrict__ scales) {
    int n = blockIdx.x;
    int c = threadIdx.x;
    float v = 0.f;
    if (c < RANK) v = lB[(size_t)c * N_TOT + n] * (1.0f / scales[0]);
    g_wb[(size_t)n * K2 + K_TOT + c] = __float2half_rn(v);
}

// ---------------------------------------------------------------------------
// Kernel 4: fp16 mma.sync GEMM, 128x128x64 tiles, TMA 3-stage pipeline
//   (byte-identical to R7 passing version — 84.2% tensor pipe)
// ---------------------------------------------------------------------------
__global__ void __launch_bounds__(GEMM_THREADS, 2) qlora_gemm_kernel(
    const __grid_constant__ CUtensorMap tmA,
    const __grid_constant__ CUtensorMap tmB,
    const float* __restrict__ scales,
    const float* __restrict__ bias,
    float* __restrict__ out)
{
    extern __shared__ __align__(1024) char smem[];
    uint32_t sb = smem_u32(smem);
    const uint32_t FULLB  = sb + OFF_FULL;
    const uint32_t EMPTYB = sb + OFF_EMPTY;
    float* sbias = (float*)(smem + OFF_BIAS);
    const uint32_t SA0 = sb + OFF_TILES;
    const uint32_t SB0 = SA0 + STAGES * TILE_BYTES;

    int tid = threadIdx.x, wid = tid >> 5, lane = tid & 31;
    int mwarp = wid >> 2, nwarp = wid & 3;

    int mt = blockIdx.x & 63;
    int nt = blockIdx.x >> 6;
    int m0 = mt * 128, n0 = nt * 128;

    if (tid == 0) {
        #pragma unroll
        for (int s = 0; s < STAGES; s++) {
            mbar_init(FULLB + 8 * s, 1);
            mbar_init(EMPTYB + 8 * s, GEMM_THREADS);
        }
        asm volatile("fence.proxy.async.shared::cta;" ::: "memory");
    }
    if (tid < 128) sbias[tid] = bias[n0 + tid];
    __syncthreads();

    if (tid == 0) {
        #pragma unroll
        for (int c = 0; c < STAGES - 1; c++) {
            mbar_expect_tx(FULLB + 8 * c, 2 * TILE_BYTES);
            tma_2d(SA0 + c * TILE_BYTES, &tmA, c * 64, m0, FULLB + 8 * c);
            tma_2d(SB0 + c * TILE_BYTES, &tmB, c * 64, n0, FULLB + 8 * c);
        }
    }

    uint32_t aRowOff[4], aSw[4];
    {
        int ar = lane & 15;
        #pragma unroll
        for (int i = 0; i < 4; i++) {
            int row = mwarp * 64 + i * 16 + ar;
            aRowOff[i] = row * 128;
            aSw[i] = row & 7;
        }
    }
    uint32_t a_dc = lane >> 4;
    uint32_t bRowOff[2], bSw[2];
    {
        #pragma unroll
        for (int jj = 0; jj < 2; jj++) {
            int row = nwarp * 32 + jj * 16 + ((lane >> 4) << 3) + (lane & 7);
            bRowOff[jj] = row * 128;
            bSw[jj] = row & 7;
        }
    }
    uint32_t b_dc = (lane >> 3) & 1;

    float acc[4][4][4];
    #pragma unroll
    for (int i = 0; i < 4; i++)
        #pragma unroll
        for (int j = 0; j < 4; j++)
            #pragma unroll
            for (int d = 0; d < 4; d++) acc[i][j][d] = 0.f;

    for (int c = 0; c < NCHUNK; c++) {
        if (tid == 0) {
            int n = c + STAGES - 1;
            if (n < NCHUNK) {
                int s = n % STAGES, r = n / STAGES;
                mbar_wait(EMPTYB + 8 * s, (r + 1) & 1);
                mbar_expect_tx(FULLB + 8 * s, 2 * TILE_BYTES);
                tma_2d(SA0 + s * TILE_BYTES, &tmA, n * 64, m0, FULLB + 8 * s);
                tma_2d(SB0 + s * TILE_BYTES, &tmB, n * 64, n0, FULLB + 8 * s);
            }
        }
        int s = c % STAGES, r = c / STAGES;
        mbar_wait(FULLB + 8 * s, r & 1);
        uint32_t sA = SA0 + s * TILE_BYTES;
        uint32_t sBw = SB0 + s * TILE_BYTES;

        #pragma unroll
        for (int ks = 0; ks < 4; ks++) {
            uint32_t cc = 2 * ks;
            uint32_t bfr[8];
            ldsm4(bfr[0], bfr[1], bfr[2], bfr[3],
                  sBw + bRowOff[0] + (((cc + b_dc) ^ bSw[0]) << 4));
            ldsm4(bfr[4], bfr[5], bfr[6], bfr[7],
                  sBw + bRowOff[1] + (((cc + b_dc) ^ bSw[1]) << 4));
            #pragma unroll
            for (int i = 0; i < 4; i++) {
                uint32_t a0, a1, a2, a3;
                ldsm4(a0, a1, a2, a3,
                      sA + aRowOff[i] + (((cc + a_dc) ^ aSw[i]) << 4));
                #pragma unroll
                for (int j = 0; j < 4; j++)
                    mma16816(acc[i][j][0], acc[i][j][1], acc[i][j][2], acc[i][j][3],
                             a0, a1, a2, a3, bfr[2 * j], bfr[2 * j + 1]);
            }
        }
        mbar_arrive(EMPTYB + 8 * s);
    }

    float scl = __ldg(scales);
    int g = lane >> 2, tig = lane & 3;
    #pragma unroll
    for (int i = 0; i < 4; i++) {
        int row = m0 + mwarp * 64 + i * 16 + g;
        #pragma unroll
        for (int j = 0; j < 4; j++) {
            int lcol = nwarp * 32 + j * 8 + tig * 2;
            float b0 = sbias[lcol], b1 = sbias[lcol + 1];
            float2 v0, v1;
            v0.x = acc[i][j][0] * scl + b0;
            v0.y = acc[i][j][1] * scl + b1;
            v1.x = acc[i][j][2] * scl + b0;
            v1.y = acc[i][j][3] * scl + b1;
            *(float2*)(out + (size_t)row * N_TOT + n0 + lcol) = v0;
            *(float2*)(out + (size_t)(row + 8) * N_TOT + n0 + lcol) = v1;
        }
    }
}

// ---------------------------------------------------------------------------
// Host launch
// ---------------------------------------------------------------------------
typedef CUresult (*PFN_encodeTiled)(
    CUtensorMap*, CUtensorMapDataType, cuuint32_t, void*,
    const cuuint64_t*, const cuuint64_t*, const cuuint32_t*, const cuuint32_t*,
    CUtensorMapInterleave, CUtensorMapSwizzle, CUtensorMapL2promotion,
    CUtensorMapFloatOOBfill);

static PFN_encodeTiled get_encoder() {
    void* fn = nullptr;
    cudaDriverEntryPointQueryResult qres = cudaDriverEntryPointSymbolNotFound;
    if (cudaGetDriverEntryPointByVersion("cuTensorMapEncodeTiled", &fn, 12000,
                                         cudaEnableDefault, &qres) == cudaSuccess &&
        qres == cudaDriverEntryPointSuccess && fn) {
        return (PFN_encodeTiled)fn;
    }
    fn = nullptr;
    qres = cudaDriverEntryPointSymbolNotFound;
    if (cudaGetDriverEntryPoint("cuTensorMapEncodeTiled", &fn,
                                cudaEnableDefault, &qres) == cudaSuccess &&
        qres == cudaDriverEntryPointSuccess && fn) {
        return (PFN_encodeTiled)fn;
    }
    return nullptr;
}

extern "C" void kernel_launch(void* const* d_in, const int* in_sizes, int n_in,
                              void* d_out, int out_size) {
    const float* x      = (const float*)d_in[0];
    const int*   qw     = (const int*)d_in[1];
    const float* scales = (const float*)d_in[2];
    const float* bias   = (const float*)d_in[3];
    const float* lA     = (const float*)d_in[4];
    const float* lB     = (const float*)d_in[5];
    float* out = (float*)d_out;

    void* p_xh = nullptr;
    void* p_wb = nullptr;
    cudaGetSymbolAddress(&p_xh, g_xh);
    cudaGetSymbolAddress(&p_wb, g_wb);

    static PFN_encodeTiled enc = nullptr;
    if (!enc) enc = get_encoder();
    if (!enc || !p_xh || !p_wb) return;

    CUtensorMap tmA, tmB;
    {
        cuuint64_t dims[2]    = {(cuuint64_t)K2, (cuuint64_t)M_TOT};
        cuuint64_t strides[1] = {(cuuint64_t)K2 * 2};
        cuuint32_t box[2]     = {64, 128};
        cuuint32_t es[2]      = {1, 1};
        if (enc(&tmA, CU_TENSOR_MAP_DATA_TYPE_FLOAT16, 2, p_xh, dims, strides, box, es,
                CU_TENSOR_MAP_INTERLEAVE_NONE, CU_TENSOR_MAP_SWIZZLE_128B,
                CU_TENSOR_MAP_L2_PROMOTION_L2_128B,
                CU_TENSOR_MAP_FLOAT_OOB_FILL_NONE) != CUDA_SUCCESS) return;
    }
    {
        cuuint64_t dims[2]    = {(cuuint64_t)K2, (cuuint64_t)N_TOT};
        cuuint64_t strides[1] = {(cuuint64_t)K2 * 2};
        cuuint32_t box[2]     = {64, 128};
        cuuint32_t es[2]      = {1, 1};
        if (enc(&tmB, CU_TENSOR_MAP_DATA_TYPE_FLOAT16, 2, p_wb, dims, strides, box, es,
                CU_TENSOR_MAP_INTERLEAVE_NONE, CU_TENSOR_MAP_SWIZZLE_128B,
                CU_TENSOR_MAP_L2_PROMOTION_L2_128B,
                CU_TENSOR_MAP_FLOAT_OOB_FILL_NONE) != CUDA_SUCCESS) return;
    }

    // 1) fused: t = x @ lora_A  AND  A-side fp16 matrix (+ tail)
    lora_prep_x_kernel<<<M_TOT / 16, 256>>>(x, lA);
    // 2) B-side fp16 main region (vectorized)
    {
        dim3 g2(2, N_TOT);
        prep_w_main_kernel<<<g2, 256>>>(qw);
    }
    // 3) B-side lora tail
    prep_w_tail_kernel<<<N_TOT, 64>>>(lB, scales);
    // 4) main GEMM
    cudaFuncSetAttribute(qlora_gemm_kernel,
                         cudaFuncAttributeMaxDynamicSharedMemorySize, SMEM_TOTAL);
    qlora_gemm_kernel<<<(M_TOT / 128) * (N_TOT / 128), GEMM_THREADS, SMEM_TOTAL>>>(
        tmA, tmB, scales, bias, out);
}

// round 9
// speedup vs baseline: 1.5440x; 1.5440x over previous
#include <cuda_runtime.h>
#include <cuda.h>
#include <cuda_fp16.h>
#include <cstdint>
#include <cstddef>
#include <cstring>

// ---------------------------------------------------------------------------
// Problem constants
// ---------------------------------------------------------------------------
#define M_TOT 8192        // B*S
#define N_TOT 4096        // D_OUT
#define K_TOT 4096        // D_IN
#define RANK  16
#define K2    4160        // K + 64 (lora tail chunk, padded)
#define NCHUNK 65         // K2 / 64
#define STAGES 3
#define GEMM_THREADS 256

// smem layout (bytes, relative to dynamic smem base; base is 1024-aligned)
#define OFF_FULL   0      // 3 x 8B
#define OFF_EMPTY  32     // 3 x 8B
#define OFF_BIAS   64     // 128 floats
#define OFF_TILES  1024
#define TILE_BYTES 16384  // 128 rows x 128B (64 fp16)
#define SMEM_TOTAL (OFF_TILES + 2 * STAGES * TILE_BYTES)   // 99328

// ---------------------------------------------------------------------------
// Device scratch (allocation-free rule: __device__ globals)
// ---------------------------------------------------------------------------
__device__ __half g_xh[(size_t)M_TOT * K2];   // [8192, 4160] fp16  ~68 MB
__device__ __half g_wb[(size_t)N_TOT * K2];   // [4096, 4160] fp16  ~34 MB

// ---------------------------------------------------------------------------
// PTX helpers (family-portable: TMA + mbarrier + ldmatrix + mma.sync only)
// ---------------------------------------------------------------------------
__device__ __forceinline__ uint32_t smem_u32(const void* p) {
    uint32_t a;
    asm("{ .reg .u64 t; cvta.to.shared.u64 t, %1; cvt.u32.u64 %0, t; }"
        : "=r"(a) : "l"(p));
    return a;
}
__device__ __forceinline__ void mbar_init(uint32_t a, uint32_t n) {
    asm volatile("mbarrier.init.shared.b64 [%0], %1;" :: "r"(a), "r"(n) : "memory");
}
__device__ __forceinline__ void mbar_expect_tx(uint32_t a, uint32_t bytes) {
    asm volatile("mbarrier.arrive.expect_tx.shared.b64 _, [%0], %1;"
                 :: "r"(a), "r"(bytes) : "memory");
}
__device__ __forceinline__ void mbar_arrive(uint32_t a) {
    asm volatile("mbarrier.arrive.shared.b64 _, [%0];" :: "r"(a) : "memory");
}
__device__ __forceinline__ void mbar_wait(uint32_t a, uint32_t parity) {
    asm volatile(
        "{\n\t.reg .pred P;\n"
        "W_%=:\n\t"
        "mbarrier.try_wait.parity.acquire.cta.shared::cta.b64 P, [%0], %1, 0x989680;\n\t"
        "@P bra D_%=;\n\t"
        "bra W_%=;\n"
        "D_%=:\n\t}"
        :: "r"(a), "r"(parity) : "memory");
}
__device__ __forceinline__ void tma_2d(uint32_t dst, const CUtensorMap* tm,
                                       int cx, int cy, uint32_t mbar) {
    asm volatile(
        "cp.async.bulk.tensor.2d.shared::cta.global.tile.mbarrier::complete_tx::bytes "
        "[%0], [%1, {%2, %3}], [%4];"
        :: "r"(dst), "l"(tm), "r"(cx), "r"(cy), "r"(mbar) : "memory");
}
__device__ __forceinline__ void ldsm4(uint32_t& r0, uint32_t& r1, uint32_t& r2,
                                      uint32_t& r3, uint32_t addr) {
    asm volatile("ldmatrix.sync.aligned.m8n8.x4.shared.b16 {%0,%1,%2,%3}, [%4];"
                 : "=r"(r0), "=r"(r1), "=r"(r2), "=r"(r3) : "r"(addr));
}
__device__ __forceinline__ void mma16816(float& d0, float& d1, float& d2, float& d3,
                                         uint32_t a0, uint32_t a1, uint32_t a2, uint32_t a3,
                                         uint32_t b0, uint32_t b1) {
    asm volatile(
        "mma.sync.aligned.m16n8k16.row.col.f32.f16.f16.f32 "
        "{%0,%1,%2,%3}, {%4,%5,%6,%7}, {%8,%9}, {%0,%1,%2,%3};"
        : "+f"(d0), "+f"(d1), "+f"(d2), "+f"(d3)
        : "r"(a0), "r"(a1), "r"(a2), "r"(a3), "r"(b0), "r"(b1));
}

// ---------------------------------------------------------------------------
// Kernel 1 (FUSED): t = x @ lora_A  AND  g_xh = fp16(x) | fp16(t) | 0
// Streams x exactly once. 16 m-rows per block, 256 threads.
// ---------------------------------------------------------------------------
__global__ void __launch_bounds__(256) lora_prep_x_kernel(const float* __restrict__ x,
                                                          const float* __restrict__ A) {
    __shared__ float sX[16][132];
    __shared__ float sAT[RANK][132];
    int tid = threadIdx.x;
    int m0 = blockIdx.x * 16;
    int ml = tid >> 4, r = tid & 15;
    float acc = 0.f;

    for (int k0 = 0; k0 < K_TOT; k0 += 128) {
        __syncthreads();
        // load x tile [16][128] as float4; also emit fp16 to g_xh from registers
        #pragma unroll
        for (int it = 0; it < 2; it++) {
            int idx = tid + it * 256;
            int row = idx >> 5, col = idx & 31;
            float4 v = ((const float4*)(x + (size_t)(m0 + row) * K_TOT + k0))[col];
            ((float4*)&sX[row][0])[col] = v;
            __half2 h01 = __floats2half2_rn(v.x, v.y);
            __half2 h23 = __floats2half2_rn(v.z, v.w);
            __half2 hp[2] = {h01, h23};
            uint2 u;
            memcpy(&u, hp, 8);
            *(uint2*)(g_xh + (size_t)(m0 + row) * K2 + k0 + col * 4) = u;
        }
        // load A chunk transposed
        #pragma unroll
        for (int it = 0; it < 2; it++) {
            int idx = tid + it * 256;
            int k = idx >> 2, q = idx & 3;
            float4 a = ((const float4*)(A + (size_t)(k0 + k) * RANK))[q];
            sAT[q * 4 + 0][k] = a.x;
            sAT[q * 4 + 1][k] = a.y;
            sAT[q * 4 + 2][k] = a.z;
            sAT[q * 4 + 3][k] = a.w;
        }
        __syncthreads();
        const float4* xr = (const float4*)&sX[ml][0];
        const float4* ar = (const float4*)&sAT[r][0];
        #pragma unroll 8
        for (int kk = 0; kk < 32; kk++) {
            float4 xv = xr[kk];
            float4 av = ar[kk];
            acc += xv.x * av.x + xv.y * av.y + xv.z * av.z + xv.w * av.w;
        }
    }
    // tail: cols [4096,4112) = fp16(t); cols [4112,4160) = 0
    g_xh[(size_t)(m0 + ml) * K2 + K_TOT + r] = __float2half_rn(acc);
    for (int j = tid; j < 16 * 48; j += 256) {
        int row = j / 48, col = j - row * 48;
        g_xh[(size_t)(m0 + row) * K2 + 4112 + col] = __ushort_as_half((unsigned short)0);
    }
}

// ---------------------------------------------------------------------------
// Kernel 2: B-side, fused main + tail. grid = (3, 4096).
//   bx<2 : vectorized int4->fp16x8 for cols [0,4096)
//   bx==2: cols [4096,4112) = fp16(lora_B[r][n]/scale); [4112,4160) = 0
// ---------------------------------------------------------------------------
__global__ void __launch_bounds__(256) prep_w_kernel(const int* __restrict__ q,
                                                     const float* __restrict__ lB,
                                                     const float* __restrict__ scales) {
    int n = blockIdx.y;
    if (blockIdx.x < 2) {
        int c0 = (blockIdx.x * 256 + threadIdx.x) * 8;
        const int4* qp = (const int4*)(q + (size_t)n * K_TOT + c0);
        int4 q0 = qp[0], q1 = qp[1];
        __half2 h[4];
        h[0] = __floats2half2_rn((float)q0.x, (float)q0.y);
        h[1] = __floats2half2_rn((float)q0.z, (float)q0.w);
        h[2] = __floats2half2_rn((float)q1.x, (float)q1.y);
        h[3] = __floats2half2_rn((float)q1.z, (float)q1.w);
        uint4 u;
        memcpy(&u, h, 16);
        *(uint4*)(g_wb + (size_t)n * K2 + c0) = u;
    } else {
        int c = threadIdx.x;
        if (c < 64) {
            float v = 0.f;
            if (c < RANK) v = lB[(size_t)c * N_TOT + n] * (1.0f / scales[0]);
            g_wb[(size_t)n * K2 + K_TOT + c] = __float2half_rn(v);
        }
    }
}

// ---------------------------------------------------------------------------
// Kernel 3: fp16 mma.sync GEMM, 128x128x64 tiles, TMA 3-stage pipeline
//   (byte-identical to R7/R8 passing version — 84% tensor pipe)
// ---------------------------------------------------------------------------
__global__ void __launch_bounds__(GEMM_THREADS, 2) qlora_gemm_kernel(
    const __grid_constant__ CUtensorMap tmA,
    const __grid_constant__ CUtensorMap tmB,
    const float* __restrict__ scales,
    const float* __restrict__ bias,
    float* __restrict__ out)
{
    extern __shared__ __align__(1024) char smem[];
    uint32_t sb = smem_u32(smem);
    const uint32_t FULLB  = sb + OFF_FULL;
    const uint32_t EMPTYB = sb + OFF_EMPTY;
    float* sbias = (float*)(smem + OFF_BIAS);
    const uint32_t SA0 = sb + OFF_TILES;
    const uint32_t SB0 = SA0 + STAGES * TILE_BYTES;

    int tid = threadIdx.x, wid = tid >> 5, lane = tid & 31;
    int mwarp = wid >> 2, nwarp = wid & 3;

    int mt = blockIdx.x & 63;
    int nt = blockIdx.x >> 6;
    int m0 = mt * 128, n0 = nt * 128;

    if (tid == 0) {
        #pragma unroll
        for (int s = 0; s < STAGES; s++) {
            mbar_init(FULLB + 8 * s, 1);
            mbar_init(EMPTYB + 8 * s, GEMM_THREADS);
        }
        asm volatile("fence.proxy.async.shared::cta;" ::: "memory");
    }
    if (tid < 128) sbias[tid] = bias[n0 + tid];
    __syncthreads();

    if (tid == 0) {
        #pragma unroll
        for (int c = 0; c < STAGES - 1; c++) {
            mbar_expect_tx(FULLB + 8 * c, 2 * TILE_BYTES);
            tma_2d(SA0 + c * TILE_BYTES, &tmA, c * 64, m0, FULLB + 8 * c);
            tma_2d(SB0 + c * TILE_BYTES, &tmB, c * 64, n0, FULLB + 8 * c);
        }
    }

    uint32_t aRowOff[4], aSw[4];
    {
        int ar = lane & 15;
        #pragma unroll
        for (int i = 0; i < 4; i++) {
            int row = mwarp * 64 + i * 16 + ar;
            aRowOff[i] = row * 128;
            aSw[i] = row & 7;
        }
    }
    uint32_t a_dc = lane >> 4;
    uint32_t bRowOff[2], bSw[2];
    {
        #pragma unroll
        for (int jj = 0; jj < 2; jj++) {
            int row = nwarp * 32 + jj * 16 + ((lane >> 4) << 3) + (lane & 7);
            bRowOff[jj] = row * 128;
            bSw[jj] = row & 7;
        }
    }
    uint32_t b_dc = (lane >> 3) & 1;

    float acc[4][4][4];
    #pragma unroll
    for (int i = 0; i < 4; i++)
        #pragma unroll
        for (int j = 0; j < 4; j++)
            #pragma unroll
            for (int d = 0; d < 4; d++) acc[i][j][d] = 0.f;

    for (int c = 0; c < NCHUNK; c++) {
        if (tid == 0) {
            int n = c + STAGES - 1;
            if (n < NCHUNK) {
                int s = n % STAGES, r = n / STAGES;
                mbar_wait(EMPTYB + 8 * s, (r + 1) & 1);
                mbar_expect_tx(FULLB + 8 * s, 2 * TILE_BYTES);
                tma_2d(SA0 + s * TILE_BYTES, &tmA, n * 64, m0, FULLB + 8 * s);
                tma_2d(SB0 + s * TILE_BYTES, &tmB, n * 64, n0, FULLB + 8 * s);
            }
        }
        int s = c % STAGES, r = c / STAGES;
        mbar_wait(FULLB + 8 * s, r & 1);
        uint32_t sA = SA0 + s * TILE_BYTES;
        uint32_t sBw = SB0 + s * TILE_BYTES;

        #pragma unroll
        for (int ks = 0; ks < 4; ks++) {
            uint32_t cc = 2 * ks;
            uint32_t bfr[8];
            ldsm4(bfr[0], bfr[1], bfr[2], bfr[3],
                  sBw + bRowOff[0] + (((cc + b_dc) ^ bSw[0]) << 4));
            ldsm4(bfr[4], bfr[5], bfr[6], bfr[7],
                  sBw + bRowOff[1] + (((cc + b_dc) ^ bSw[1]) << 4));
            #pragma unroll
            for (int i = 0; i < 4; i++) {
                uint32_t a0, a1, a2, a3;
                ldsm4(a0, a1, a2, a3,
                      sA + aRowOff[i] + (((cc + a_dc) ^ aSw[i]) << 4));
                #pragma unroll
                for (int j = 0; j < 4; j++)
                    mma16816(acc[i][j][0], acc[i][j][1], acc[i][j][2], acc[i][j][3],
                             a0, a1, a2, a3, bfr[2 * j], bfr[2 * j + 1]);
            }
        }
        mbar_arrive(EMPTYB + 8 * s);
    }

    float scl = __ldg(scales);
    int g = lane >> 2, tig = lane & 3;
    #pragma unroll
    for (int i = 0; i < 4; i++) {
        int row = m0 + mwarp * 64 + i * 16 + g;
        #pragma unroll
        for (int j = 0; j < 4; j++) {
            int lcol = nwarp * 32 + j * 8 + tig * 2;
            float b0 = sbias[lcol], b1 = sbias[lcol + 1];
            float2 v0, v1;
            v0.x = acc[i][j][0] * scl + b0;
            v0.y = acc[i][j][1] * scl + b1;
            v1.x = acc[i][j][2] * scl + b0;
            v1.y = acc[i][j][3] * scl + b1;
            *(float2*)(out + (size_t)row * N_TOT + n0 + lcol) = v0;
            *(float2*)(out + (size_t)(row + 8) * N_TOT + n0 + lcol) = v1;
        }
    }
}

// ---------------------------------------------------------------------------
// Host launch
// ---------------------------------------------------------------------------
typedef CUresult (*PFN_encodeTiled)(
    CUtensorMap*, CUtensorMapDataType, cuuint32_t, void*,
    const cuuint64_t*, const cuuint64_t*, const cuuint32_t*, const cuuint32_t*,
    CUtensorMapInterleave, CUtensorMapSwizzle, CUtensorMapL2promotion,
    CUtensorMapFloatOOBfill);

static PFN_encodeTiled get_encoder() {
    void* fn = nullptr;
    cudaDriverEntryPointQueryResult qres = cudaDriverEntryPointSymbolNotFound;
    if (cudaGetDriverEntryPointByVersion("cuTensorMapEncodeTiled", &fn, 12000,
                                         cudaEnableDefault, &qres) == cudaSuccess &&
        qres == cudaDriverEntryPointSuccess && fn) {
        return (PFN_encodeTiled)fn;
    }
    fn = nullptr;
    qres = cudaDriverEntryPointSymbolNotFound;
    if (cudaGetDriverEntryPoint("cuTensorMapEncodeTiled", &fn,
                                cudaEnableDefault, &qres) == cudaSuccess &&
        qres == cudaDriverEntryPointSuccess && fn) {
        return (PFN_encodeTiled)fn;
    }
    return nullptr;
}

extern "C" void kernel_launch(void* const* d_in, const int* in_sizes, int n_in,
                              void* d_out, int out_size) {
    const float* x      = (const float*)d_in[0];
    const int*   qw     = (const int*)d_in[1];
    const float* scales = (const float*)d_in[2];
    const float* bias   = (const float*)d_in[3];
    const float* lA     = (const float*)d_in[4];
    const float* lB     = (const float*)d_in[5];
    float* out = (float*)d_out;

    void* p_xh = nullptr;
    void* p_wb = nullptr;
    cudaGetSymbolAddress(&p_xh, g_xh);
    cudaGetSymbolAddress(&p_wb, g_wb);

    static PFN_encodeTiled enc = nullptr;
    if (!enc) enc = get_encoder();
    if (!enc || !p_xh || !p_wb) return;

    CUtensorMap tmA, tmB;
    {
        cuuint64_t dims[2]    = {(cuuint64_t)K2, (cuuint64_t)M_TOT};
        cuuint64_t strides[1] = {(cuuint64_t)K2 * 2};
        cuuint32_t box[2]     = {64, 128};
        cuuint32_t es[2]      = {1, 1};
        if (enc(&tmA, CU_TENSOR_MAP_DATA_TYPE_FLOAT16, 2, p_xh, dims, strides, box, es,
                CU_TENSOR_MAP_INTERLEAVE_NONE, CU_TENSOR_MAP_SWIZZLE_128B,
                CU_TENSOR_MAP_L2_PROMOTION_L2_128B,
                CU_TENSOR_MAP_FLOAT_OOB_FILL_NONE) != CUDA_SUCCESS) return;
    }
    {
        cuuint64_t dims[2]    = {(cuuint64_t)K2, (cuuint64_t)N_TOT};
        cuuint64_t strides[1] = {(cuuint64_t)K2 * 2};
        cuuint32_t box[2]     = {64, 128};
        cuuint32_t es[2]      = {1, 1};
        if (enc(&tmB, CU_TENSOR_MAP_DATA_TYPE_FLOAT16, 2, p_wb, dims, strides, box, es,
                CU_TENSOR_MAP_INTERLEAVE_NONE, CU_TENSOR_MAP_SWIZZLE_128B,
                CU_TENSOR_MAP_L2_PROMOTION_L2_128B,
                CU_TENSOR_MAP_FLOAT_OOB_FILL_NONE) != CUDA_SUCCESS) return;
    }

    // 1) fused: t = x @ lora_A  AND  A-side fp16 matrix (+ tail)
    lora_prep_x_kernel<<<M_TOT / 16, 256>>>(x, lA);
    // 2) B-side fp16 (main region + lora tail, fused)
    {
        dim3 g2(3, N_TOT);
        prep_w_kernel<<<g2, 256>>>(qw, lB, scales);
    }
    // 3) main GEMM
    cudaFuncSetAttribute(qlora_gemm_kernel,
                         cudaFuncAttributeMaxDynamicSharedMemorySize, SMEM_TOTAL);
    qlora_gemm_kernel<<<(M_TOT / 128) * (N_TOT / 128), GEMM_THREADS, SMEM_TOTAL>>>(
        tmA, tmB, scales, bias, out);
}

// round 10
// speedup vs baseline: 1.7646x; 1.1429x over previous
#include <cuda_runtime.h>
#include <cuda.h>
#include <cuda_fp16.h>
#include <cstdint>
#include <cstddef>
#include <cstring>

// ---------------------------------------------------------------------------
// Problem constants
// ---------------------------------------------------------------------------
#define M_TOT 8192        // B*S
#define N_TOT 4096        // D_OUT
#define K_TOT 4096        // D_IN
#define RANK  16
#define K2    4096        // LoRA folded into weights -> no K padding needed
#define NCHUNK 64         // K2 / 64
#define STAGES 3
#define GEMM_THREADS 256

// smem layout (bytes, relative to dynamic smem base; base is 1024-aligned)
#define OFF_FULL   0      // 3 x 8B
#define OFF_EMPTY  32     // 3 x 8B
#define OFF_BIAS   64     // 128 floats
#define OFF_TILES  1024
#define TILE_BYTES 16384  // 128 rows x 128B (64 fp16)
#define SMEM_TOTAL (OFF_TILES + 2 * STAGES * TILE_BYTES)   // 99328

// ---------------------------------------------------------------------------
// Device scratch (allocation-free rule: __device__ globals)
// ---------------------------------------------------------------------------
__device__ __half g_xh[(size_t)M_TOT * K2];   // [8192, 4096] fp16  64 MB
__device__ __half g_wb[(size_t)N_TOT * K2];   // [4096, 4096] fp16  32 MB

// ---------------------------------------------------------------------------
// PTX helpers (family-portable: TMA + mbarrier + ldmatrix + mma.sync only)
// ---------------------------------------------------------------------------
__device__ __forceinline__ uint32_t smem_u32(const void* p) {
    uint32_t a;
    asm("{ .reg .u64 t; cvta.to.shared.u64 t, %1; cvt.u32.u64 %0, t; }"
        : "=r"(a) : "l"(p));
    return a;
}
__device__ __forceinline__ void mbar_init(uint32_t a, uint32_t n) {
    asm volatile("mbarrier.init.shared.b64 [%0], %1;" :: "r"(a), "r"(n) : "memory");
}
__device__ __forceinline__ void mbar_expect_tx(uint32_t a, uint32_t bytes) {
    asm volatile("mbarrier.arrive.expect_tx.shared.b64 _, [%0], %1;"
                 :: "r"(a), "r"(bytes) : "memory");
}
__device__ __forceinline__ void mbar_arrive(uint32_t a) {
    asm volatile("mbarrier.arrive.shared.b64 _, [%0];" :: "r"(a) : "memory");
}
__device__ __forceinline__ void mbar_wait(uint32_t a, uint32_t parity) {
    asm volatile(
        "{\n\t.reg .pred P;\n"
        "W_%=:\n\t"
        "mbarrier.try_wait.parity.acquire.cta.shared::cta.b64 P, [%0], %1, 0x989680;\n\t"
        "@P bra D_%=;\n\t"
        "bra W_%=;\n"
        "D_%=:\n\t}"
        :: "r"(a), "r"(parity) : "memory");
}
__device__ __forceinline__ void tma_2d(uint32_t dst, const CUtensorMap* tm,
                                       int cx, int cy, uint32_t mbar) {
    asm volatile(
        "cp.async.bulk.tensor.2d.shared::cta.global.tile.mbarrier::complete_tx::bytes "
        "[%0], [%1, {%2, %3}], [%4];"
        :: "r"(dst), "l"(tm), "r"(cx), "r"(cy), "r"(mbar) : "memory");
}
__device__ __forceinline__ void ldsm4(uint32_t& r0, uint32_t& r1, uint32_t& r2,
                                      uint32_t& r3, uint32_t addr) {
    asm volatile("ldmatrix.sync.aligned.m8n8.x4.shared.b16 {%0,%1,%2,%3}, [%4];"
                 : "=r"(r0), "=r"(r1), "=r"(r2), "=r"(r3) : "r"(addr));
}
__device__ __forceinline__ void mma16816(float& d0, float& d1, float& d2, float& d3,
                                         uint32_t a0, uint32_t a1, uint32_t a2, uint32_t a3,
                                         uint32_t b0, uint32_t b1) {
    asm volatile(
        "mma.sync.aligned.m16n8k16.row.col.f32.f16.f16.f32 "
        "{%0,%1,%2,%3}, {%4,%5,%6,%7}, {%8,%9}, {%0,%1,%2,%3};"
        : "+f"(d0), "+f"(d1), "+f"(d2), "+f"(d3)
        : "r"(a0), "r"(a1), "r"(a2), "r"(a3), "r"(b0), "r"(b1));
}

// ---------------------------------------------------------------------------
// Kernel 1: pure stream convert  g_xh = fp16(x).  8 elements / thread.
// ---------------------------------------------------------------------------
__global__ void __launch_bounds__(256) conv_x_kernel(const float* __restrict__ x) {
    size_t i = ((size_t)blockIdx.x * 256 + threadIdx.x) * 8;
    float4 v0 = *(const float4*)(x + i);
    float4 v1 = *(const float4*)(x + i + 4);
    __half2 h[4];
    h[0] = __floats2half2_rn(v0.x, v0.y);
    h[1] = __floats2half2_rn(v0.z, v0.w);
    h[2] = __floats2half2_rn(v1.x, v1.y);
    h[3] = __floats2half2_rn(v1.z, v1.w);
    uint4 u;
    memcpy(&u, h, 16);
    *(uint4*)(g_xh + i) = u;
}

// ---------------------------------------------------------------------------
// Kernel 2: W_eff[n][k] = fp16( q[n][k] + (1/scale) * sum_r A[k][r]*B[r][n] )
//   grid (K_TOT/128, N_TOT/32), 256 threads.
//   Thread map: tn = tid&15 (2 n each), tk = tid>>4 (8 k each)
//   -> A smem reads are warp-broadcast (lanes 0-15 share tk) : conflict-free.
// ---------------------------------------------------------------------------
#define PW_TK 128
#define PW_TN 32
__global__ void __launch_bounds__(256) prep_w_kernel(const int* __restrict__ q,
                                                     const float* __restrict__ lA,
                                                     const float* __restrict__ lB,
                                                     const float* __restrict__ scales) {
    __shared__ float sA[PW_TK][16];   // A[k][r] tile, 8KB
    __shared__ float sB[16][PW_TN];   // (B*c)[r][n] tile, 2KB
    int tid = threadIdx.x;
    int k0 = blockIdx.x * PW_TK, n0 = blockIdx.y * PW_TN;
    float c = 1.0f / __ldg(scales);

    #pragma unroll
    for (int it = 0; it < 2; it++) {
        int idx = tid + it * 256;          // 0..511 float4 (A rows = 4 float4)
        int k = idx >> 2, qd = idx & 3;
        float4 a = ((const float4*)(lA + (size_t)(k0 + k) * RANK))[qd];
        sA[k][qd * 4 + 0] = a.x;
        sA[k][qd * 4 + 1] = a.y;
        sA[k][qd * 4 + 2] = a.z;
        sA[k][qd * 4 + 3] = a.w;
    }
    if (tid < 128) {                       // 16 rows x 8 float4
        int r = tid >> 3, qd = tid & 7;
        float4 b = ((const float4*)(lB + (size_t)r * N_TOT + n0))[qd];
        sB[r][qd * 4 + 0] = b.x * c;
        sB[r][qd * 4 + 1] = b.y * c;
        sB[r][qd * 4 + 2] = b.z * c;
        sB[r][qd * 4 + 3] = b.w * c;
    }
    __syncthreads();

    int tn = tid & 15, tk = tid >> 4;
    float bb[2][16];
    #pragma unroll
    for (int nn = 0; nn < 2; nn++)
        #pragma unroll
        for (int r = 0; r < 16; r++) bb[nn][r] = sB[r][tn * 2 + nn];

    int qa[2][8];
    #pragma unroll
    for (int nn = 0; nn < 2; nn++) {
        int n = n0 + tn * 2 + nn;
        const int4* qp = (const int4*)(q + (size_t)n * K_TOT + k0 + tk * 8);
        int4 u0 = qp[0], u1 = qp[1];
        qa[nn][0] = u0.x; qa[nn][1] = u0.y; qa[nn][2] = u0.z; qa[nn][3] = u0.w;
        qa[nn][4] = u1.x; qa[nn][5] = u1.y; qa[nn][6] = u1.z; qa[nn][7] = u1.w;
    }

    __half2 owt[2][4];
    float wprev[2];
    #pragma unroll
    for (int kk = 0; kk < 8; kk++) {
        const float4* ap = (const float4*)&sA[tk * 8 + kk][0];
        float4 a0 = ap[0], a1 = ap[1], a2 = ap[2], a3 = ap[3];
        float av[16] = {a0.x, a0.y, a0.z, a0.w, a1.x, a1.y, a1.z, a1.w,
                        a2.x, a2.y, a2.z, a2.w, a3.x, a3.y, a3.z, a3.w};
        #pragma unroll
        for (int nn = 0; nn < 2; nn++) {
            float s0 = 0.f, s1 = 0.f;
            #pragma unroll
            for (int r = 0; r < 16; r += 2) {
                s0 = fmaf(av[r], bb[nn][r], s0);
                s1 = fmaf(av[r + 1], bb[nn][r + 1], s1);
            }
            float w = (float)qa[nn][kk] + (s0 + s1);
            if (kk & 1) owt[nn][kk >> 1] = __floats2half2_rn(wprev[nn], w);
            else        wprev[nn] = w;
        }
    }
    #pragma unroll
    for (int nn = 0; nn < 2; nn++) {
        int n = n0 + tn * 2 + nn;
        uint4 u;
        memcpy(&u, owt[nn], 16);
        *(uint4*)(g_wb + (size_t)n * K2 + k0 + tk * 8) = u;
    }
}

// ---------------------------------------------------------------------------
// Kernel 3: fp16 mma.sync GEMM, 128x128x64 tiles, TMA 3-stage pipeline
//   (identical structure to R7/R9 passing version — 84% tensor pipe; K=4096)
// ---------------------------------------------------------------------------
__global__ void __launch_bounds__(GEMM_THREADS, 2) qlora_gemm_kernel(
    const __grid_constant__ CUtensorMap tmA,
    const __grid_constant__ CUtensorMap tmB,
    const float* __restrict__ scales,
    const float* __restrict__ bias,
    float* __restrict__ out)
{
    extern __shared__ __align__(1024) char smem[];
    uint32_t sb = smem_u32(smem);
    const uint32_t FULLB  = sb + OFF_FULL;
    const uint32_t EMPTYB = sb + OFF_EMPTY;
    float* sbias = (float*)(smem + OFF_BIAS);
    const uint32_t SA0 = sb + OFF_TILES;
    const uint32_t SB0 = SA0 + STAGES * TILE_BYTES;

    int tid = threadIdx.x, wid = tid >> 5, lane = tid & 31;
    int mwarp = wid >> 2, nwarp = wid & 3;

    int mt = blockIdx.x & 63;
    int nt = blockIdx.x >> 6;
    int m0 = mt * 128, n0 = nt * 128;

    if (tid == 0) {
        #pragma unroll
        for (int s = 0; s < STAGES; s++) {
            mbar_init(FULLB + 8 * s, 1);
            mbar_init(EMPTYB + 8 * s, GEMM_THREADS);
        }
        asm volatile("fence.proxy.async.shared::cta;" ::: "memory");
    }
    if (tid < 128) sbias[tid] = bias[n0 + tid];
    __syncthreads();

    if (tid == 0) {
        #pragma unroll
        for (int c = 0; c < STAGES - 1; c++) {
            mbar_expect_tx(FULLB + 8 * c, 2 * TILE_BYTES);
            tma_2d(SA0 + c * TILE_BYTES, &tmA, c * 64, m0, FULLB + 8 * c);
            tma_2d(SB0 + c * TILE_BYTES, &tmB, c * 64, n0, FULLB + 8 * c);
        }
    }

    uint32_t aRowOff[4], aSw[4];
    {
        int ar = lane & 15;
        #pragma unroll
        for (int i = 0; i < 4; i++) {
            int row = mwarp * 64 + i * 16 + ar;
            aRowOff[i] = row * 128;
            aSw[i] = row & 7;
        }
    }
    uint32_t a_dc = lane >> 4;
    uint32_t bRowOff[2], bSw[2];
    {
        #pragma unroll
        for (int jj = 0; jj < 2; jj++) {
            int row = nwarp * 32 + jj * 16 + ((lane >> 4) << 3) + (lane & 7);
            bRowOff[jj] = row * 128;
            bSw[jj] = row & 7;
        }
    }
    uint32_t b_dc = (lane >> 3) & 1;

    float acc[4][4][4];
    #pragma unroll
    for (int i = 0; i < 4; i++)
        #pragma unroll
        for (int j = 0; j < 4; j++)
            #pragma unroll
            for (int d = 0; d < 4; d++) acc[i][j][d] = 0.f;

    for (int c = 0; c < NCHUNK; c++) {
        if (tid == 0) {
            int n = c + STAGES - 1;
            if (n < NCHUNK) {
                int s = n % STAGES, r = n / STAGES;
                mbar_wait(EMPTYB + 8 * s, (r + 1) & 1);
                mbar_expect_tx(FULLB + 8 * s, 2 * TILE_BYTES);
                tma_2d(SA0 + s * TILE_BYTES, &tmA, n * 64, m0, FULLB + 8 * s);
                tma_2d(SB0 + s * TILE_BYTES, &tmB, n * 64, n0, FULLB + 8 * s);
            }
        }
        int s = c % STAGES, r = c / STAGES;
        mbar_wait(FULLB + 8 * s, r & 1);
        uint32_t sA = SA0 + s * TILE_BYTES;
        uint32_t sBw = SB0 + s * TILE_BYTES;

        #pragma unroll
        for (int ks = 0; ks < 4; ks++) {
            uint32_t cc = 2 * ks;
            uint32_t bfr[8];
            ldsm4(bfr[0], bfr[1], bfr[2], bfr[3],
                  sBw + bRowOff[0] + (((cc + b_dc) ^ bSw[0]) << 4));
            ldsm4(bfr[4], bfr[5], bfr[6], bfr[7],
                  sBw + bRowOff[1] + (((cc + b_dc) ^ bSw[1]) << 4));
            #pragma unroll
            for (int i = 0; i < 4; i++) {
                uint32_t a0, a1, a2, a3;
                ldsm4(a0, a1, a2, a3,
                      sA + aRowOff[i] + (((cc + a_dc) ^ aSw[i]) << 4));
                #pragma unroll
                for (int j = 0; j < 4; j++)
                    mma16816(acc[i][j][0], acc[i][j][1], acc[i][j][2], acc[i][j][3],
                             a0, a1, a2, a3, bfr[2 * j], bfr[2 * j + 1]);
            }
        }
        mbar_arrive(EMPTYB + 8 * s);
    }

    float scl = __ldg(scales);
    int g = lane >> 2, tig = lane & 3;
    #pragma unroll
    for (int i = 0; i < 4; i++) {
        int row = m0 + mwarp * 64 + i * 16 + g;
        #pragma unroll
        for (int j = 0; j < 4; j++) {
            int lcol = nwarp * 32 + j * 8 + tig * 2;
            float b0 = sbias[lcol], b1 = sbias[lcol + 1];
            float2 v0, v1;
            v0.x = acc[i][j][0] * scl + b0;
            v0.y = acc[i][j][1] * scl + b1;
            v1.x = acc[i][j][2] * scl + b0;
            v1.y = acc[i][j][3] * scl + b1;
            *(float2*)(out + (size_t)row * N_TOT + n0 + lcol) = v0;
            *(float2*)(out + (size_t)(row + 8) * N_TOT + n0 + lcol) = v1;
        }
    }
}

// ---------------------------------------------------------------------------
// Host launch
// ---------------------------------------------------------------------------
typedef CUresult (*PFN_encodeTiled)(
    CUtensorMap*, CUtensorMapDataType, cuuint32_t, void*,
    const cuuint64_t*, const cuuint64_t*, const cuuint32_t*, const cuuint32_t*,
    CUtensorMapInterleave, CUtensorMapSwizzle, CUtensorMapL2promotion,
    CUtensorMapFloatOOBfill);

static PFN_encodeTiled get_encoder() {
    void* fn = nullptr;
    cudaDriverEntryPointQueryResult qres = cudaDriverEntryPointSymbolNotFound;
    if (cudaGetDriverEntryPointByVersion("cuTensorMapEncodeTiled", &fn, 12000,
                                         cudaEnableDefault, &qres) == cudaSuccess &&
        qres == cudaDriverEntryPointSuccess && fn) {
        return (PFN_encodeTiled)fn;
    }
    fn = nullptr;
    qres = cudaDriverEntryPointSymbolNotFound;
    if (cudaGetDriverEntryPoint("cuTensorMapEncodeTiled", &fn,
                                cudaEnableDefault, &qres) == cudaSuccess &&
        qres == cudaDriverEntryPointSuccess && fn) {
        return (PFN_encodeTiled)fn;
    }
    return nullptr;
}

extern "C" void kernel_launch(void* const* d_in, const int* in_sizes, int n_in,
                              void* d_out, int out_size) {
    const float* x      = (const float*)d_in[0];
    const int*   qw     = (const int*)d_in[1];
    const float* scales = (const float*)d_in[2];
    const float* bias   = (const float*)d_in[3];
    const float* lA     = (const float*)d_in[4];
    const float* lB     = (const float*)d_in[5];
    float* out = (float*)d_out;

    void* p_xh = nullptr;
    void* p_wb = nullptr;
    cudaGetSymbolAddress(&p_xh, g_xh);
    cudaGetSymbolAddress(&p_wb, g_wb);

    static PFN_encodeTiled enc = nullptr;
    if (!enc) enc = get_encoder();
    if (!enc || !p_xh || !p_wb) return;

    CUtensorMap tmA, tmB;
    {
        cuuint64_t dims[2]    = {(cuuint64_t)K2, (cuuint64_t)M_TOT};
        cuuint64_t strides[1] = {(cuuint64_t)K2 * 2};
        cuuint32_t box[2]     = {64, 128};
        cuuint32_t es[2]      = {1, 1};
        if (enc(&tmA, CU_TENSOR_MAP_DATA_TYPE_FLOAT16, 2, p_xh, dims, strides, box, es,
                CU_TENSOR_MAP_INTERLEAVE_NONE, CU_TENSOR_MAP_SWIZZLE_128B,
                CU_TENSOR_MAP_L2_PROMOTION_L2_128B,
                CU_TENSOR_MAP_FLOAT_OOB_FILL_NONE) != CUDA_SUCCESS) return;
    }
    {
        cuuint64_t dims[2]    = {(cuuint64_t)K2, (cuuint64_t)N_TOT};
        cuuint64_t strides[1] = {(cuuint64_t)K2 * 2};
        cuuint32_t box[2]     = {64, 128};
        cuuint32_t es[2]      = {1, 1};
        if (enc(&tmB, CU_TENSOR_MAP_DATA_TYPE_FLOAT16, 2, p_wb, dims, strides, box, es,
                CU_TENSOR_MAP_INTERLEAVE_NONE, CU_TENSOR_MAP_SWIZZLE_128B,
                CU_TENSOR_MAP_L2_PROMOTION_L2_128B,
                CU_TENSOR_MAP_FLOAT_OOB_FILL_NONE) != CUDA_SUCCESS) return;
    }

    // 1) x -> fp16 (pure stream)
    conv_x_kernel<<<(unsigned)((size_t)M_TOT * K_TOT / 8 / 256), 256>>>(x);
    // 2) W_eff = q + (1/scale) * (A@B)^T  -> fp16
    {
        dim3 g2(K_TOT / PW_TK, N_TOT / PW_TN);
        prep_w_kernel<<<g2, 256>>>(qw, lA, lB, scales);
    }
    // 3) main GEMM
    cudaFuncSetAttribute(qlora_gemm_kernel,
                         cudaFuncAttributeMaxDynamicSharedMemorySize, SMEM_TOTAL);
    qlora_gemm_kernel<<<(M_TOT / 128) * (N_TOT / 128), GEMM_THREADS, SMEM_TOTAL>>>(
        tmA, tmB, scales, bias, out);
}